// round 15
// baseline (speedup 1.0000x reference)
#include <cuda_runtime.h>

#define L      512
#define NT     128
#define NSIG   4096
#define NTOT   (32*512*128)

typedef unsigned long long ull;

__device__ float g_omega[NSIG * 2];
__device__ int   g_swap[32];

// ---- packed f32x2 helpers (complex = (re, im) in one 64-bit reg pair) ----
__device__ __forceinline__ ull pk2(float x, float y) {
    ull r; asm("mov.b64 %0,{%1,%2};" : "=l"(r) : "f"(x), "f"(y)); return r;
}
__device__ __forceinline__ void up2(ull a, float& x, float& y) {
    asm("mov.b64 {%0,%1},%2;" : "=f"(x), "=f"(y) : "l"(a));
}
__device__ __forceinline__ ull padd(ull a, ull b) {
    ull r; asm("add.rn.f32x2 %0,%1,%2;" : "=l"(r) : "l"(a), "l"(b)); return r;
}
__device__ __forceinline__ ull pfma(ull a, ull b, ull c) {
    ull r; asm("fma.rn.f32x2 %0,%1,%2,%3;" : "=l"(r) : "l"(a), "l"(b), "l"(c)); return r;
}
__device__ __forceinline__ ull psub(ull a, ull b, ull NEG1) { return pfma(b, NEG1, a); }
template<int SGN>
__device__ __forceinline__ ull pmuli(ull a) {
    float x, y; up2(a, x, y);
    return (SGN > 0) ? pk2(-y, x) : pk2(y, -x);
}
__device__ __forceinline__ ull pcmul(ull a, float wr, float wi) {
    float x, y; up2(a, x, y);
    return pk2(x * wr - y * wi, x * wi + y * wr);
}

// warp-wide reduce of a packed f32x2 pair (both lanes summed independently)
__device__ __forceinline__ ull preduce(ull v) {
#pragma unroll
    for (int o = 16; o; o >>= 1)
        v = padd(v, __shfl_xor_sync(0xffffffffu, v, o));
    return v;
}

// 256-pt Stockham FFT, radices (8,8,4). X0 -> X1 -> X2 -> X3 (ull-aliased float2).
// SPLIT-STAGE layout: stages 0 and 1 each run on warps 0+1 — both warps load
// all 8 butterfly inputs and the shared first layer; warp 0 emits the even
// outputs (p=0,2,4,6), warp 1 the odd (p=1,3,5,7). Stage 2 runs on warps 2+3.
// If OM: warp 2 folds the 256 raw float2 partials into om_s in the stage-0 window.
// X0/X3 natural; X1 XOR-swizzled; X2 padded (k + 72j). Conflict-free per warp.
// Tables hold INVERSE twiddles; SGN=-1 conjugates => forward. No 1/N scaling.
// First action is __syncthreads(); trailing sync.
template<int SGN, bool OM>
__device__ __forceinline__ void fft256(ull* X0, ull* X1, ull* X2, ull* X3,
                                       const float2* tw0, const float2* tw1, int tid,
                                       const ull* raw, float* om_s) {
    const ull NEG1 = pk2(-1.0f, -1.0f);
    const float S2 = 0.70710678118654752f;
    __syncthreads();
    if (OM && (tid >> 5) == 2) {
        int ln = tid & 31;
        ull s0 = padd(padd(raw[ln], raw[ln + 32]), padd(raw[ln + 64], raw[ln + 96]));
        ull s1 = padd(padd(raw[ln + 128], raw[ln + 160]), padd(raw[ln + 192], raw[ln + 224]));
        s0 = preduce(s0);
        s1 = preduce(s1);
        if (ln == 0) {
            float a, bb, c, dd;
            up2(s0, a, bb); up2(s1, c, dd);
            om_s[0] = __fdividef(a, bb + 1e-7f);
            om_s[1] = __fdividef(c, dd + 1e-7f);
        }
    }
    if (tid < 64) {                 // stage 0: radix-8 split, X0 -> X1
        const int j = tid & 31, hf = tid >> 5;
        ull c[8];
#pragma unroll
        for (int q = 0; q < 8; q++) c[q] = X0[j + 32 * q];
        ull t0 = padd(c[0], c[4]), t1 = psub(c[0], c[4], NEG1);
        ull t2 = padd(c[2], c[6]), t3 = pmuli<SGN>(psub(c[2], c[6], NEG1));
        ull u0 = padd(c[1], c[5]), u1 = psub(c[1], c[5], NEG1);
        ull u2 = padd(c[3], c[7]), u3 = pmuli<SGN>(psub(c[3], c[7], NEG1));
        const float2* tp = tw0 + 7 * j;
        const int s = (j >> 1) & 7;
        ull* st = X1 + 8 * j;
        if (hf == 0) {              // even outputs p = 0,2,4,6
            ull E0 = padd(t0, t2), E2 = psub(t0, t2, NEG1);
            ull O0 = padd(u0, u2), o2 = pmuli<SGN>(psub(u0, u2, NEG1));
            ull d0 = padd(E0, O0);
            ull d4 = psub(E0, O0, NEG1);
            ull d2 = padd(E2, o2);
            ull d6 = psub(E2, o2, NEG1);
            float2 w;
            w = tp[1]; d2 = pcmul(d2, w.x, (SGN > 0) ? w.y : -w.y);
            w = tp[3]; d4 = pcmul(d4, w.x, (SGN > 0) ? w.y : -w.y);
            w = tp[5]; d6 = pcmul(d6, w.x, (SGN > 0) ? w.y : -w.y);
            st[0 ^ s] = d0; st[2 ^ s] = d2; st[4 ^ s] = d4; st[6 ^ s] = d6;
        } else {                    // odd outputs p = 1,3,5,7
            ull E1 = padd(t1, t3), E3 = psub(t1, t3, NEG1);
            ull O1 = padd(u1, u3), O3 = psub(u1, u3, NEG1);
            ull o1 = pcmul(O1, S2, (SGN > 0) ? S2 : -S2);
            ull o3 = pcmul(O3, -S2, (SGN > 0) ? S2 : -S2);
            ull d1 = padd(E1, o1);
            ull d5 = psub(E1, o1, NEG1);
            ull d3 = padd(E3, o3);
            ull d7 = psub(E3, o3, NEG1);
            float2 w;
            w = tp[0]; d1 = pcmul(d1, w.x, (SGN > 0) ? w.y : -w.y);
            w = tp[2]; d3 = pcmul(d3, w.x, (SGN > 0) ? w.y : -w.y);
            w = tp[4]; d5 = pcmul(d5, w.x, (SGN > 0) ? w.y : -w.y);
            w = tp[6]; d7 = pcmul(d7, w.x, (SGN > 0) ? w.y : -w.y);
            st[1 ^ s] = d1; st[3 ^ s] = d3; st[5 ^ s] = d5; st[7 ^ s] = d7;
        }
    }
    __syncthreads();
    if (tid < 64) {                 // stage 1: radix-8 split, X1 -> X2
        const int tt = tid & 31, hf = tid >> 5;
        const int j = tt >> 3, k = tt & 7;
        ull c[8];
#pragma unroll
        for (int q = 0; q < 8; q++) { int l = tt + 32 * q; c[q] = X1[l ^ ((l >> 4) & 7)]; }
        ull t0 = padd(c[0], c[4]), t1 = psub(c[0], c[4], NEG1);
        ull t2 = padd(c[2], c[6]), t3 = pmuli<SGN>(psub(c[2], c[6], NEG1));
        ull u0 = padd(c[1], c[5]), u1 = psub(c[1], c[5], NEG1);
        ull u2 = padd(c[3], c[7]), u3 = pmuli<SGN>(psub(c[3], c[7], NEG1));
        const float2* tp = tw1 + 7 * j;
        ull* st = X2 + (k + 72 * j);
        if (hf == 0) {
            ull E0 = padd(t0, t2), E2 = psub(t0, t2, NEG1);
            ull O0 = padd(u0, u2), o2 = pmuli<SGN>(psub(u0, u2, NEG1));
            ull d0 = padd(E0, O0);
            ull d4 = psub(E0, O0, NEG1);
            ull d2 = padd(E2, o2);
            ull d6 = psub(E2, o2, NEG1);
            float2 w;
            w = tp[1]; d2 = pcmul(d2, w.x, (SGN > 0) ? w.y : -w.y);
            w = tp[3]; d4 = pcmul(d4, w.x, (SGN > 0) ? w.y : -w.y);
            w = tp[5]; d6 = pcmul(d6, w.x, (SGN > 0) ? w.y : -w.y);
            st[0]  = d0; st[16] = d2; st[32] = d4; st[48] = d6;
        } else {
            ull E1 = padd(t1, t3), E3 = psub(t1, t3, NEG1);
            ull O1 = padd(u1, u3), O3 = psub(u1, u3, NEG1);
            ull o1 = pcmul(O1, S2, (SGN > 0) ? S2 : -S2);
            ull o3 = pcmul(O3, -S2, (SGN > 0) ? S2 : -S2);
            ull d1 = padd(E1, o1);
            ull d5 = psub(E1, o1, NEG1);
            ull d3 = padd(E3, o3);
            ull d7 = psub(E3, o3, NEG1);
            float2 w;
            w = tp[0]; d1 = pcmul(d1, w.x, (SGN > 0) ? w.y : -w.y);
            w = tp[2]; d3 = pcmul(d3, w.x, (SGN > 0) ? w.y : -w.y);
            w = tp[4]; d5 = pcmul(d5, w.x, (SGN > 0) ? w.y : -w.y);
            w = tp[6]; d7 = pcmul(d7, w.x, (SGN > 0) ? w.y : -w.y);
            st[8]  = d1; st[24] = d3; st[40] = d5; st[56] = d7;
        }
    }
    __syncthreads();
    if (tid >= 64) {                // stage 2: radix-4 on warps 2,3: X2 -> X3
        const int k = tid - 64;
        ull c[4];
#pragma unroll
        for (int q = 0; q < 4; q++) c[q] = X2[k + 72 * q];
        ull t0 = padd(c[0], c[2]), t1 = psub(c[0], c[2], NEG1);
        ull t2 = padd(c[1], c[3]), t3 = pmuli<SGN>(psub(c[1], c[3], NEG1));
        X3[k]       = padd(t0, t2);
        X3[k + 64]  = padd(t1, t3);
        X3[k + 128] = psub(t0, t2, NEG1);
        X3[k + 192] = psub(t1, t3, NEG1);
    }
    __syncthreads();
}

// Pack ifft input for a Hermitian spectrum H (H2=conj(H1), H3=conj(H0) generic;
// t0: H0,H2 real, H3=conj(H1)). In[k1] = E1 + i*(D1*wA);
// In[k2]: generic (E1r+O1i, O1r-E1i), t0 (2H1r, -2H1i).
__device__ __forceinline__ void pack_store(float2* X0, int k1v, int k2v, bool isT0,
                                           float wAr, float wAi,
                                           float H0r, float H0i, float H1r, float H1i,
                                           float H2r, float H2i) {
    float E1r = H0r + H2r, E1i = H0i + H2i;
    float D1r = H0r - H2r, D1i = H0i - H2i;
    float O1r = D1r * wAr - D1i * wAi, O1i = D1r * wAi + D1i * wAr;
    X0[k1v] = make_float2(E1r - O1i, E1i + O1r);
    float gr = E1r + O1i, gi = O1r - E1i;
    X0[k2v] = make_float2(isT0 ? 2.0f * H1r : gr, isT0 ? -2.0f * H1i : gi);
}

// One CTA = one (b,d) signal. Spectra register-resident; thread wt owns bins
// {wt, 256-wt, 256+wt, 512-wt} (wt=0: {0,128,256,384}). kx=Herm(U1) carried
// across iterations; Herm slots 2,3 by conjugation. Block reduction offloaded
// to warp 2 (during FFT stage 0). Last iteration skips fft/lambda/pack.
__global__ void __launch_bounds__(NT, 8) vmd_main(const float* __restrict__ x,
                                                  float* __restrict__ out) {
    __shared__ float2 X0[256], X1[256], X2[280], X3[256];
    __shared__ float2 tw0s[224], tw1s[28];
    __shared__ float2 raw2[256];       // (n0,den0)[tid], (n1,den1)[tid+128]
    __shared__ float om_s[2];
    __shared__ float xs_s[512];        // xs_s[slot*128 + tid]
    __shared__ float2 wa_s[128];       // wA per thread
    ull* X0u = reinterpret_cast<ull*>(X0);
    ull* X1u = reinterpret_cast<ull*>(X1);
    ull* X2u = reinterpret_cast<ull*>(X2);
    ull* X3u = reinterpret_cast<ull*>(X3);
    ull* rawu = reinterpret_cast<ull*>(raw2);

    const int tid = threadIdx.x;
    const int sig = blockIdx.x;
    const int b = sig >> 7, d = sig & 127;
    const float* xp = x + (size_t)b * 65536 + d;

    // inverse twiddle tables: tw0[7j+p-1]=cis(2pi j p/256) j<32; tw1: /32, j<4
    for (int idx = tid; idx < 224 + 28; idx += NT) {
        if (idx < 224) {
            int j = idx / 7, pm = idx - 7 * j + 1;
            float sv, cv;
            sincosf(6.283185307179586f * (float)(j * pm) * (1.0f / 256.0f), &sv, &cv);
            tw0s[idx] = make_float2(cv, sv);
        } else {
            int r = idx - 224;
            int j = r / 7, pm = r - 7 * j + 1;
            float sv, cv;
            sincosf(6.283185307179586f * (float)(j * pm) * (1.0f / 32.0f), &sv, &cv);
            tw1s[r] = make_float2(cv, sv);
        }
    }

    const bool isT0 = (tid == 0);
    const int tv0 = isT0 ? 0   : tid;
    const int tv1 = isT0 ? 128 : 256 - tid;
    const int tv2 = isT0 ? 256 : 256 + tid;
    const int tv3 = isT0 ? 384 : 512 - tid;
    const float f0 = (float)tv0 * (1.0f / 512.0f);
    const float f1 = (float)tv1 * (1.0f / 512.0f);
    const float f2 = (float)(tv2 - 512) * (1.0f / 512.0f);
    const float f3 = (float)(tv3 - 512) * (1.0f / 512.0f);
    const int k1 = tv0;            // packs slots (0,2)
    const int k2 = tv1 & 255;      // packs slots (1,3)
    const int g0 = tv0 >> 1, g1 = tv1 >> 1, g2 = tv2 >> 1, g3 = tv3 >> 1;
    const int odd = tv0 & 1;
    float wBr, wBi;   // prologue-only
    {
        float ar, ai;
        sincosf(6.283185307179586f * f0, &ai, &ar);
        sincosf(6.283185307179586f * f1, &wBi, &wBr);
        wa_s[tid] = make_float2(ar, ai);
        xs_s[tid]       = xp[(size_t)tv0 * 128];
        xs_s[tid + 128] = xp[(size_t)tv1 * 128];
        xs_s[tid + 256] = xp[(size_t)tv2 * 128];
        xs_s[tid + 384] = xp[(size_t)tv3 * 128];
    }

    // forward: pack z[m] = x[2m] + i x[2m+1], one 256-pt forward FFT
#pragma unroll
    for (int m = tid; m < 256; m += NT) {
        float ev = xp[(size_t)(2 * m) * 128];
        float ov = xp[(size_t)(2 * m + 1) * 128];
        X0[m] = make_float2(ev, ov);
    }
    fft256<-1, false>(X0u, X1u, X2u, X3u, tw0s, tw1s, tid, rawu, om_s);
    float X0r, X0i, X1r, X1i, X2r, X2i, X3r, X3i;
    {
        float2 wA = wa_s[tid];
        float2 Zt = X3[k1], Zk = X3[k2];
        float2 M1 = isT0 ? Zt : Zk;
        float2 M2 = isT0 ? Zk : Zt;
        float Er = 0.5f * (Zt.x + M1.x), Ei = 0.5f * (Zt.y - M1.y);
        float Dr = Zt.x - M1.x,         Di = Zt.y + M1.y;
        float Or = 0.5f * Di,           Oi = -0.5f * Dr;
        float cr = wA.x * Or + wA.y * Oi, ci = wA.x * Oi - wA.y * Or;
        X0r = Er + cr; X0i = Ei + ci;
        X2r = Er - cr; X2i = Ei - ci;
        float Er2 = 0.5f * (Zk.x + M2.x), Ei2 = 0.5f * (Zk.y - M2.y);
        float Dr2 = Zk.x - M2.x,          Di2 = Zk.y + M2.y;
        float Or2 = 0.5f * Di2,           Oi2 = -0.5f * Dr2;
        float cr2 = wBr * Or2 + wBi * Oi2, ci2 = wBr * Oi2 - wBi * Or2;
        X1r = Er2 + cr2; X1i = Ei2 + ci2;
        X3r = Er2 - cr2; X3i = Ei2 - ci2;
    }

    // loop-carried: kx = Herm(U1) (init 0), h = Herm(U0) (epilogue use)
    float kx0r = 0.f, kx0i = 0.f, kx1r = 0.f, kx1i = 0.f;
    float kx2r = 0.f, kx2i = 0.f, kx3r = 0.f, kx3i = 0.f;
    float h0r = 0.f, h0i = 0.f, h1r = 0.f, h1i = 0.f;
    float h2r = 0.f, h2i = 0.f, h3r = 0.f, h3i = 0.f;
    float l0 = 0.f, l1 = 0.f, l2 = 0.f, l3 = 0.f;
    float om0 = 0.0f, om1 = 0.0f;
    const float* z3f = reinterpret_cast<const float*>(X3);

    for (int iter = 0; iter < 50; iter++) {
        // ---- Pass A (mirror-free): U0 = (X - kx + lam'/2) * q0
        float df, q;
        float u0r0, u0i0, u0r1, u0i1, u0r2, u0i2, u0r3, u0i3;
        df = f0 - om0; q = __frcp_rn(fmaf(1600.0f * df, df, 1.0f));
        u0r0 = (X0r - kx0r + 0.5f * l2) * q; u0i0 = (X0i - kx0i) * q;
        df = f1 - om0; q = __frcp_rn(fmaf(1600.0f * df, df, 1.0f));
        u0r1 = (X1r - kx1r + 0.5f * l3) * q; u0i1 = (X1i - kx1i) * q;
        df = f2 - om0; q = __frcp_rn(fmaf(1600.0f * df, df, 1.0f));
        u0r2 = (X2r - kx2r + 0.5f * l0) * q; u0i2 = (X2i - kx2i) * q;
        df = f3 - om0; q = __frcp_rn(fmaf(1600.0f * df, df, 1.0f));
        u0r3 = (X3r - kx3r + 0.5f * l1) * q; u0i3 = (X3i - kx3i) * q;

        // ---- Pass B: h = Herm(U0) via conj pairing; omega0 partials; U1 update
        {
            float m0r = isT0 ? u0r0 : u0r3, m0i = isT0 ? u0i0 : u0i3;
            float m1r = isT0 ? u0r3 : u0r2, m1i = isT0 ? u0i3 : u0i2;
            h0r = 0.5f * (u0r0 + m0r); h0i = 0.5f * (u0i0 - m0i);
            h1r = 0.5f * (u0r1 + m1r); h1i = 0.5f * (u0i1 - m1i);
            h2r = isT0 ? u0r2 : h1r;   h2i = isT0 ? 0.0f : -h1i;
            h3r = isT0 ? h1r : h0r;    h3i = -(isT0 ? h1i : h0i);
        }
        float p0 = h0r * h0r + h0i * h0i;
        float p1 = h1r * h1r + h1i * h1i;
        raw2[tid] = make_float2(f0 * p0 + f1 * p1, p0 + p1);
        float u1r0, u1i0, u1r1, u1i1, u1r2, u1i2, u1r3, u1i3;
        df = f0 - om1; q = __frcp_rn(fmaf(1600.0f * df, df, 1.0f));
        u1r0 = (X0r - h0r + 0.5f * l2) * q; u1i0 = (X0i - h0i) * q;
        df = f1 - om1; q = __frcp_rn(fmaf(1600.0f * df, df, 1.0f));
        u1r1 = (X1r - h1r + 0.5f * l3) * q; u1i1 = (X1i - h1i) * q;
        df = f2 - om1; q = __frcp_rn(fmaf(1600.0f * df, df, 1.0f));
        u1r2 = (X2r - h2r + 0.5f * l0) * q; u1i2 = (X2i - h2i) * q;
        df = f3 - om1; q = __frcp_rn(fmaf(1600.0f * df, df, 1.0f));
        u1r3 = (X3r - h3r + 0.5f * l1) * q; u1i3 = (X3i - h3i) * q;

        // ---- Pass C: kx = Herm(U1) via conj pairing; omega1 partials; pack & scatter
        {
            float m0r = isT0 ? u1r0 : u1r3, m0i = isT0 ? u1i0 : u1i3;
            float m1r = isT0 ? u1r3 : u1r2, m1i = isT0 ? u1i3 : u1i2;
            kx0r = 0.5f * (u1r0 + m0r); kx0i = 0.5f * (u1i0 - m0i);
            kx1r = 0.5f * (u1r1 + m1r); kx1i = 0.5f * (u1i1 - m1i);
            kx2r = isT0 ? u1r2 : kx1r;  kx2i = isT0 ? 0.0f : -kx1i;
            kx3r = isT0 ? kx1r : kx0r;  kx3i = -(isT0 ? kx1i : kx0i);
        }
        p0 = kx0r * kx0r + kx0i * kx0i;
        p1 = kx1r * kx1r + kx1i * kx1i;
        raw2[tid + 128] = make_float2(f0 * p0 + f1 * p1, p0 + p1);

        if (iter < 49) {
            {
                float2 wA = wa_s[tid];
                float H0r = h0r + kx0r, H0i = h0i + kx0i;
                float H1r = h1r + kx1r, H1i = h1i + kx1i;
                float H2r = h2r + kx2r, H2i = h2i + kx2i;
                pack_store(X0, k1, k2, isT0, wA.x, wA.y,
                           H0r, H0i, H1r, H1i, H2r, H2i);
            }
            fft256<+1, true>(X0u, X1u, X2u, X3u, tw0s, tw1s, tid, rawu, om_s);
            om0 = om_s[0];
            om1 = om_s[1];
            // lam += tau*(x - h/512);  h[tv] = z[tv>>1].{x|y} by parity
            l0 = fmaf(0.001f, xs_s[tid]       - z3f[2 * g0 + odd] * (1.0f / 512.0f), l0);
            l1 = fmaf(0.001f, xs_s[tid + 128] - z3f[2 * g1 + odd] * (1.0f / 512.0f), l1);
            l2 = fmaf(0.001f, xs_s[tid + 256] - z3f[2 * g2 + odd] * (1.0f / 512.0f), l2);
            l3 = fmaf(0.001f, xs_s[tid + 384] - z3f[2 * g3 + odd] * (1.0f / 512.0f), l3);
        }
    }

    // final omega from the iter-49 partials (warp 0, one time)
    __syncthreads();
    if (tid < 32) {
        ull s0 = padd(padd(rawu[tid], rawu[tid + 32]), padd(rawu[tid + 64], rawu[tid + 96]));
        ull s1 = padd(padd(rawu[tid + 128], rawu[tid + 160]), padd(rawu[tid + 192], rawu[tid + 224]));
        s0 = preduce(s0);
        s1 = preduce(s1);
        if (tid == 0) {
            float a, bb, c, dd;
            up2(s0, a, bb); up2(s1, c, dd);
            g_omega[sig * 2 + 0] = __fdividef(a, bb + 1e-7f);
            g_omega[sig * 2 + 1] = __fdividef(c, dd + 1e-7f);
        }
    }

    // ---- outputs: which=0 -> ifft(h)=u0(t), which=1 -> ifft(kx)=u1(t)
#pragma unroll 1
    for (int which = 0; which < 2; which++) {
        float2 wA = wa_s[tid];
        float H0r = which ? kx0r : h0r, H0i = which ? kx0i : h0i;
        float H1r = which ? kx1r : h1r, H1i = which ? kx1i : h1i;
        float H2r = which ? kx2r : h2r, H2i = which ? kx2i : h2i;
        pack_store(X0, k1, k2, isT0, wA.x, wA.y,
                   H0r, H0i, H1r, H1i, H2r, H2i);
        fft256<+1, false>(X0u, X1u, X2u, X3u, tw0s, tw1s, tid, rawu, om_s);
        float* o = out + (size_t)(which + 1) * NTOT + (size_t)b * 65536 + d;
        o[(size_t)tv0 * 128] = z3f[2 * g0 + odd] * (1.0f / 512.0f);
        o[(size_t)tv1 * 128] = z3f[2 * g1 + odd] * (1.0f / 512.0f);
        o[(size_t)tv2 * 128] = z3f[2 * g2 + odd] * (1.0f / 512.0f);
        o[(size_t)tv3 * 128] = z3f[2 * g3 + odd] * (1.0f / 512.0f);
    }
}

// order[b]: argsort over K=2 of mean_d(omega). Stable: swap iff m1 < m0.
__global__ void order_kernel() {
    __shared__ float sm[64];
    int tid = threadIdx.x;
    if (tid < 64) {
        int b = tid >> 1, k = tid & 1;
        float s = 0.0f;
        for (int dd = 0; dd < 128; dd++)
            s += g_omega[((b << 7) + dd) * 2 + k];
        sm[tid] = s;
    }
    __syncthreads();
    if (tid < 32) g_swap[tid] = (sm[2 * tid + 1] < sm[2 * tid]) ? 1 : 0;
}

// zero x_trend; swap period/res segments where needed
__global__ void finalize_kernel(float* __restrict__ out) {
    int e = blockIdx.x * blockDim.x + threadIdx.x;
    if (e < NTOT) {
        out[e] = 0.0f;
        int b = e >> 16;
        if (g_swap[b]) {
            float a = out[NTOT + e];
            float c = out[2 * NTOT + e];
            out[NTOT + e] = c;
            out[2 * NTOT + e] = a;
        }
    }
}

extern "C" void kernel_launch(void* const* d_in, const int* in_sizes, int n_in,
                              void* d_out, int out_size) {
    const float* x = (const float*)d_in[0];
    float* out = (float*)d_out;
    vmd_main<<<NSIG, NT>>>(x, out);
    order_kernel<<<1, 64>>>();
    finalize_kernel<<<(NTOT + 255) / 256, 256>>>(out);
}

// round 16
// speedup vs baseline: 1.0174x; 1.0174x over previous
#include <cuda_runtime.h>

#define L      512
#define NT     128
#define NSIG   4096
#define NTOT   (32*512*128)

typedef unsigned long long ull;

__device__ float g_omega[NSIG * 2];
__device__ int   g_swap[32];

// ---- packed f32x2 helpers (complex = (re, im) in one 64-bit reg pair) ----
__device__ __forceinline__ ull pk2(float x, float y) {
    ull r; asm("mov.b64 %0,{%1,%2};" : "=l"(r) : "f"(x), "f"(y)); return r;
}
__device__ __forceinline__ void up2(ull a, float& x, float& y) {
    asm("mov.b64 {%0,%1},%2;" : "=f"(x), "=f"(y) : "l"(a));
}
__device__ __forceinline__ ull padd(ull a, ull b) {
    ull r; asm("add.rn.f32x2 %0,%1,%2;" : "=l"(r) : "l"(a), "l"(b)); return r;
}
__device__ __forceinline__ ull pfma(ull a, ull b, ull c) {
    ull r; asm("fma.rn.f32x2 %0,%1,%2,%3;" : "=l"(r) : "l"(a), "l"(b), "l"(c)); return r;
}
__device__ __forceinline__ ull psub(ull a, ull b, ull NEG1) { return pfma(b, NEG1, a); }
template<int SGN>
__device__ __forceinline__ ull pmuli(ull a) {
    float x, y; up2(a, x, y);
    return (SGN > 0) ? pk2(-y, x) : pk2(y, -x);
}
__device__ __forceinline__ ull pcmul(ull a, float wr, float wi) {
    float x, y; up2(a, x, y);
    return pk2(x * wr - y * wi, x * wi + y * wr);
}

// warp-wide reduce of a packed f32x2 pair (both lanes summed independently)
__device__ __forceinline__ ull preduce(ull v) {
#pragma unroll
    for (int o = 16; o; o >>= 1)
        v = padd(v, __shfl_xor_sync(0xffffffffu, v, o));
    return v;
}

template<int SGN>
__device__ __forceinline__ void bfly8p(const ull c[8], ull dd[8], ull NEG1) {
    const float S2 = 0.70710678118654752f;
    ull t0 = padd(c[0], c[4]), t1 = psub(c[0], c[4], NEG1);
    ull t2 = padd(c[2], c[6]), t3 = pmuli<SGN>(psub(c[2], c[6], NEG1));
    ull u0 = padd(c[1], c[5]), u1 = psub(c[1], c[5], NEG1);
    ull u2 = padd(c[3], c[7]), u3 = pmuli<SGN>(psub(c[3], c[7], NEG1));
    ull E0 = padd(t0, t2), E2 = psub(t0, t2, NEG1);
    ull E1 = padd(t1, t3), E3 = psub(t1, t3, NEG1);
    ull O0 = padd(u0, u2), O2 = psub(u0, u2, NEG1);
    ull O1 = padd(u1, u3), O3 = psub(u1, u3, NEG1);
    ull o1 = pcmul(O1, S2, (SGN > 0) ? S2 : -S2);
    ull o2 = pmuli<SGN>(O2);
    ull o3 = pcmul(O3, -S2, (SGN > 0) ? S2 : -S2);
    dd[0] = padd(E0, O0); dd[4] = psub(E0, O0, NEG1);
    dd[1] = padd(E1, o1); dd[5] = psub(E1, o1, NEG1);
    dd[2] = padd(E2, o2); dd[6] = psub(E2, o2, NEG1);
    dd[3] = padd(E3, o3); dd[7] = psub(E3, o3, NEG1);
}

// 256-pt Stockham FFT, radices (8,8,4). X0 -> X1 -> X2 -> X3 (ull-aliased float2).
// Stages 0,1 on warp 0; stage 2 on warps 2,3 (tid>=64). X0/X3 natural;
// X1 XOR-swizzled; X2 padded (k + 72j). All LDS/STS conflict-free.
// Tables hold INVERSE twiddles; SGN=-1 conjugates => forward. No 1/N scaling.
// If OM: warp 2 folds the 256 raw float2 partials into om_s in the stage-0 window.
// If LAM: stage-2 threads fuse the lambda recursion using their register z values:
//   lam2[m] += tau*xs2[m] - (tau/512)*z[m]   (packed per time-pair)
// First action is __syncthreads(); trailing sync.
template<int SGN, bool OM, bool LAM>
__device__ __forceinline__ void fft256(ull* X0, ull* X1, ull* X2, ull* X3,
                                       const float2* tw0, const float2* tw1, int tid,
                                       const ull* raw, float* om_s,
                                       ull* lam2, const ull* xs2) {
    const ull NEG1 = pk2(-1.0f, -1.0f);
    __syncthreads();
    if (OM && (tid >> 5) == 2) {
        int ln = tid & 31;
        ull s0 = padd(padd(raw[ln], raw[ln + 32]), padd(raw[ln + 64], raw[ln + 96]));
        ull s1 = padd(padd(raw[ln + 128], raw[ln + 160]), padd(raw[ln + 192], raw[ln + 224]));
        s0 = preduce(s0);
        s1 = preduce(s1);
        if (ln == 0) {
            float a, bb, c, dd;
            up2(s0, a, bb); up2(s1, c, dd);
            om_s[0] = __fdividef(a, bb + 1e-7f);
            om_s[1] = __fdividef(c, dd + 1e-7f);
        }
    }
    if (tid < 32) {                 // stage 0: radix-8, X0 -> X1 (warp 0)
        ull c[8], dd[8];
#pragma unroll
        for (int q = 0; q < 8; q++) c[q] = X0[tid + 32 * q];
        bfly8p<SGN>(c, dd, NEG1);
        const float2* tp = tw0 + 7 * tid;
#pragma unroll
        for (int p = 1; p < 8; p++) {
            float2 w = tp[p - 1];
            dd[p] = pcmul(dd[p], w.x, (SGN > 0) ? w.y : -w.y);
        }
        const int s = (tid >> 1) & 7;
        ull* st = X1 + 8 * tid;
#pragma unroll
        for (int p = 0; p < 8; p++) st[p ^ s] = dd[p];
    }
    __syncthreads();
    if (tid < 32) {                 // stage 1: radix-8, X1 -> X2 (warp 0)
        const int j = tid >> 3, k = tid & 7;
        ull c[8], dd[8];
#pragma unroll
        for (int q = 0; q < 8; q++) { int l = tid + 32 * q; c[q] = X1[l ^ ((l >> 4) & 7)]; }
        bfly8p<SGN>(c, dd, NEG1);
        const float2* tp = tw1 + 7 * j;
#pragma unroll
        for (int p = 1; p < 8; p++) {
            float2 w = tp[p - 1];
            dd[p] = pcmul(dd[p], w.x, (SGN > 0) ? w.y : -w.y);
        }
        ull* st = X2 + (k + 72 * j);
#pragma unroll
        for (int p = 0; p < 8; p++) st[8 * p] = dd[p];
    }
    __syncthreads();
    if (tid >= 64) {                // stage 2: radix-4, X2 -> X3 (warps 2,3)
        const int k = tid - 64;
        ull c[4];
#pragma unroll
        for (int q = 0; q < 4; q++) c[q] = X2[k + 72 * q];
        ull t0 = padd(c[0], c[2]), t1 = psub(c[0], c[2], NEG1);
        ull t2 = padd(c[1], c[3]), t3 = pmuli<SGN>(psub(c[1], c[3], NEG1));
        ull z0 = padd(t0, t2);
        ull z1 = padd(t1, t3);
        ull z2 = psub(t0, t2, NEG1);
        ull z3 = psub(t1, t3, NEG1);
        X3[k]       = z0;
        X3[k + 64]  = z1;
        X3[k + 128] = z2;
        X3[k + 192] = z3;
        if (LAM) {
            const ull TAU   = pk2(0.001f, 0.001f);
            const ull NT512 = pk2(-0.001f / 512.0f, -0.001f / 512.0f);
            lam2[k]       = pfma(z0, NT512, pfma(xs2[k],       TAU, lam2[k]));
            lam2[k + 64]  = pfma(z1, NT512, pfma(xs2[k + 64],  TAU, lam2[k + 64]));
            lam2[k + 128] = pfma(z2, NT512, pfma(xs2[k + 128], TAU, lam2[k + 128]));
            lam2[k + 192] = pfma(z3, NT512, pfma(xs2[k + 192], TAU, lam2[k + 192]));
        }
    }
    __syncthreads();
}

// Pack ifft input for a Hermitian spectrum H (H2=conj(H1), H3=conj(H0) generic;
// t0: H0,H2 real, H3=conj(H1)). In[k1] = E1 + i*(D1*wA);
// In[k2]: generic (E1r+O1i, O1r-E1i), t0 (2H1r, -2H1i).
__device__ __forceinline__ void pack_store(float2* X0, int k1v, int k2v, bool isT0,
                                           float wAr, float wAi,
                                           float H0r, float H0i, float H1r, float H1i,
                                           float H2r, float H2i) {
    float E1r = H0r + H2r, E1i = H0i + H2i;
    float D1r = H0r - H2r, D1i = H0i - H2i;
    float O1r = D1r * wAr - D1i * wAi, O1i = D1r * wAi + D1i * wAr;
    X0[k1v] = make_float2(E1r - O1i, E1i + O1r);
    float gr = E1r + O1i, gi = O1r - E1i;
    X0[k2v] = make_float2(isT0 ? 2.0f * H1r : gr, isT0 ? -2.0f * H1i : gi);
}

// One CTA = one (b,d) signal. Spectra register-resident; thread wt owns bins
// {wt, 256-wt, 256+wt, 512-wt} (wt=0: {0,128,256,384}). kx=Herm(U1) carried
// across iterations; Herm slots 2,3 by conjugation. Omega reduction on warp 2,
// lambda recursion fused into stage 2 (warps 2,3) — both off the all-thread
// path. Last iteration skips fft/lambda/pack.
__global__ void __launch_bounds__(NT, 8) vmd_main(const float* __restrict__ x,
                                                  float* __restrict__ out) {
    __shared__ float2 X0[256], X1[256], X2[280], X3[256];
    __shared__ float2 tw0s[224], tw1s[28];
    __shared__ float2 raw2[256];       // (n0,den0)[tid], (n1,den1)[tid+128]
    __shared__ float om_s[2];
    __shared__ float2 xs2[256];        // xs2[m] = (x[2m], x[2m+1])
    __shared__ float2 lam2[256];       // lam2[m] = (lam[2m], lam[2m+1])
    __shared__ float2 wa_s[128];       // wA per thread
    ull* X0u = reinterpret_cast<ull*>(X0);
    ull* X1u = reinterpret_cast<ull*>(X1);
    ull* X2u = reinterpret_cast<ull*>(X2);
    ull* X3u = reinterpret_cast<ull*>(X3);
    ull* rawu = reinterpret_cast<ull*>(raw2);
    ull* lamu = reinterpret_cast<ull*>(lam2);
    ull* xsu = reinterpret_cast<ull*>(xs2);
    const float* lamf = reinterpret_cast<const float*>(lam2);

    const int tid = threadIdx.x;
    const int sig = blockIdx.x;
    const int b = sig >> 7, d = sig & 127;
    const float* xp = x + (size_t)b * 65536 + d;

    // inverse twiddle tables: tw0[7j+p-1]=cis(2pi j p/256) j<32; tw1: /32, j<4
    for (int idx = tid; idx < 224 + 28; idx += NT) {
        if (idx < 224) {
            int j = idx / 7, pm = idx - 7 * j + 1;
            float sv, cv;
            sincosf(6.283185307179586f * (float)(j * pm) * (1.0f / 256.0f), &sv, &cv);
            tw0s[idx] = make_float2(cv, sv);
        } else {
            int r = idx - 224;
            int j = r / 7, pm = r - 7 * j + 1;
            float sv, cv;
            sincosf(6.283185307179586f * (float)(j * pm) * (1.0f / 32.0f), &sv, &cv);
            tw1s[r] = make_float2(cv, sv);
        }
    }

    const bool isT0 = (tid == 0);
    const int tv0 = isT0 ? 0   : tid;
    const int tv1 = isT0 ? 128 : 256 - tid;
    const int tv2 = isT0 ? 256 : 256 + tid;
    const int tv3 = isT0 ? 384 : 512 - tid;
    const float f0 = (float)tv0 * (1.0f / 512.0f);
    const float f1 = (float)tv1 * (1.0f / 512.0f);
    const float f2 = (float)(tv2 - 512) * (1.0f / 512.0f);
    const float f3 = (float)(tv3 - 512) * (1.0f / 512.0f);
    const int k1 = tv0;            // packs slots (0,2)
    const int k2 = tv1 & 255;      // packs slots (1,3)
    const int g0 = tv0 >> 1, g1 = tv1 >> 1, g2 = tv2 >> 1, g3 = tv3 >> 1;
    const int odd = tv0 & 1;
    float wBr, wBi;   // prologue-only
    {
        float ar, ai;
        sincosf(6.283185307179586f * f0, &ai, &ar);
        sincosf(6.283185307179586f * f1, &wBi, &wBr);
        wa_s[tid] = make_float2(ar, ai);
    }

    // prologue loads: xs2[m] and forward FFT input X0[m] = x[2m] + i x[2m+1];
    // zero lam2.
#pragma unroll
    for (int m = tid; m < 256; m += NT) {
        float ev = xp[(size_t)(2 * m) * 128];
        float ov = xp[(size_t)(2 * m + 1) * 128];
        float2 v = make_float2(ev, ov);
        xs2[m] = v;
        X0[m] = v;
        lam2[m] = make_float2(0.0f, 0.0f);
    }
    fft256<-1, false, false>(X0u, X1u, X2u, X3u, tw0s, tw1s, tid, rawu, om_s, lamu, xsu);
    float X0r, X0i, X1r, X1i, X2r, X2i, X3r, X3i;
    {
        float2 wA = wa_s[tid];
        float2 Zt = X3[k1], Zk = X3[k2];
        float2 M1 = isT0 ? Zt : Zk;
        float2 M2 = isT0 ? Zk : Zt;
        float Er = 0.5f * (Zt.x + M1.x), Ei = 0.5f * (Zt.y - M1.y);
        float Dr = Zt.x - M1.x,         Di = Zt.y + M1.y;
        float Or = 0.5f * Di,           Oi = -0.5f * Dr;
        float cr = wA.x * Or + wA.y * Oi, ci = wA.x * Oi - wA.y * Or;
        X0r = Er + cr; X0i = Ei + ci;
        X2r = Er - cr; X2i = Ei - ci;
        float Er2 = 0.5f * (Zk.x + M2.x), Ei2 = 0.5f * (Zk.y - M2.y);
        float Dr2 = Zk.x - M2.x,          Di2 = Zk.y + M2.y;
        float Or2 = 0.5f * Di2,           Oi2 = -0.5f * Dr2;
        float cr2 = wBr * Or2 + wBi * Oi2, ci2 = wBr * Oi2 - wBi * Or2;
        X1r = Er2 + cr2; X1i = Ei2 + ci2;
        X3r = Er2 - cr2; X3i = Ei2 - ci2;
    }

    // loop-carried: kx = Herm(U1) (init 0), h = Herm(U0) (epilogue use)
    float kx0r = 0.f, kx0i = 0.f, kx1r = 0.f, kx1i = 0.f;
    float kx2r = 0.f, kx2i = 0.f, kx3r = 0.f, kx3i = 0.f;
    float h0r = 0.f, h0i = 0.f, h1r = 0.f, h1i = 0.f;
    float h2r = 0.f, h2i = 0.f, h3r = 0.f, h3i = 0.f;
    float om0 = 0.0f, om1 = 0.0f;
    const float* z3f = reinterpret_cast<const float*>(X3);

    for (int iter = 0; iter < 50; iter++) {
        // lambda values (updated by stage-2 threads last iter): lam[t] = lamf[t]
        float la0 = lamf[tv2];   // for slot 0 (bin tv0 uses lam at tv0^256)
        float la1 = lamf[tv3];
        float la2 = lamf[tv0];
        float la3 = lamf[tv1];

        // ---- Pass A (mirror-free): U0 = (X - kx + lam'/2) * q0
        float df, q;
        float u0r0, u0i0, u0r1, u0i1, u0r2, u0i2, u0r3, u0i3;
        df = f0 - om0; q = __frcp_rn(fmaf(1600.0f * df, df, 1.0f));
        u0r0 = (X0r - kx0r + 0.5f * la0) * q; u0i0 = (X0i - kx0i) * q;
        df = f1 - om0; q = __frcp_rn(fmaf(1600.0f * df, df, 1.0f));
        u0r1 = (X1r - kx1r + 0.5f * la1) * q; u0i1 = (X1i - kx1i) * q;
        df = f2 - om0; q = __frcp_rn(fmaf(1600.0f * df, df, 1.0f));
        u0r2 = (X2r - kx2r + 0.5f * la2) * q; u0i2 = (X2i - kx2i) * q;
        df = f3 - om0; q = __frcp_rn(fmaf(1600.0f * df, df, 1.0f));
        u0r3 = (X3r - kx3r + 0.5f * la3) * q; u0i3 = (X3i - kx3i) * q;

        // ---- Pass B: h = Herm(U0) via conj pairing; omega0 partials; U1 update
        {
            float m0r = isT0 ? u0r0 : u0r3, m0i = isT0 ? u0i0 : u0i3;
            float m1r = isT0 ? u0r3 : u0r2, m1i = isT0 ? u0i3 : u0i2;
            h0r = 0.5f * (u0r0 + m0r); h0i = 0.5f * (u0i0 - m0i);
            h1r = 0.5f * (u0r1 + m1r); h1i = 0.5f * (u0i1 - m1i);
            h2r = isT0 ? u0r2 : h1r;   h2i = isT0 ? 0.0f : -h1i;
            h3r = isT0 ? h1r : h0r;    h3i = -(isT0 ? h1i : h0i);
        }
        float p0 = h0r * h0r + h0i * h0i;
        float p1 = h1r * h1r + h1i * h1i;
        raw2[tid] = make_float2(f0 * p0 + f1 * p1, p0 + p1);
        float u1r0, u1i0, u1r1, u1i1, u1r2, u1i2, u1r3, u1i3;
        df = f0 - om1; q = __frcp_rn(fmaf(1600.0f * df, df, 1.0f));
        u1r0 = (X0r - h0r + 0.5f * la0) * q; u1i0 = (X0i - h0i) * q;
        df = f1 - om1; q = __frcp_rn(fmaf(1600.0f * df, df, 1.0f));
        u1r1 = (X1r - h1r + 0.5f * la1) * q; u1i1 = (X1i - h1i) * q;
        df = f2 - om1; q = __frcp_rn(fmaf(1600.0f * df, df, 1.0f));
        u1r2 = (X2r - h2r + 0.5f * la2) * q; u1i2 = (X2i - h2i) * q;
        df = f3 - om1; q = __frcp_rn(fmaf(1600.0f * df, df, 1.0f));
        u1r3 = (X3r - h3r + 0.5f * la3) * q; u1i3 = (X3i - h3i) * q;

        // ---- Pass C: kx = Herm(U1) via conj pairing; omega1 partials; pack & scatter
        {
            float m0r = isT0 ? u1r0 : u1r3, m0i = isT0 ? u1i0 : u1i3;
            float m1r = isT0 ? u1r3 : u1r2, m1i = isT0 ? u1i3 : u1i2;
            kx0r = 0.5f * (u1r0 + m0r); kx0i = 0.5f * (u1i0 - m0i);
            kx1r = 0.5f * (u1r1 + m1r); kx1i = 0.5f * (u1i1 - m1i);
            kx2r = isT0 ? u1r2 : kx1r;  kx2i = isT0 ? 0.0f : -kx1i;
            kx3r = isT0 ? kx1r : kx0r;  kx3i = -(isT0 ? kx1i : kx0i);
        }
        p0 = kx0r * kx0r + kx0i * kx0i;
        p1 = kx1r * kx1r + kx1i * kx1i;
        raw2[tid + 128] = make_float2(f0 * p0 + f1 * p1, p0 + p1);

        if (iter < 49) {
            {
                float2 wA = wa_s[tid];
                float H0r = h0r + kx0r, H0i = h0i + kx0i;
                float H1r = h1r + kx1r, H1i = h1i + kx1i;
                float H2r = h2r + kx2r, H2i = h2i + kx2i;
                pack_store(X0, k1, k2, isT0, wA.x, wA.y,
                           H0r, H0i, H1r, H1i, H2r, H2i);
            }
            fft256<+1, true, true>(X0u, X1u, X2u, X3u, tw0s, tw1s, tid, rawu, om_s, lamu, xsu);
            om0 = om_s[0];
            om1 = om_s[1];
        }
    }

    // final omega from the iter-49 partials (warp 0, one time)
    __syncthreads();
    if (tid < 32) {
        ull s0 = padd(padd(rawu[tid], rawu[tid + 32]), padd(rawu[tid + 64], rawu[tid + 96]));
        ull s1 = padd(padd(rawu[tid + 128], rawu[tid + 160]), padd(rawu[tid + 192], rawu[tid + 224]));
        s0 = preduce(s0);
        s1 = preduce(s1);
        if (tid == 0) {
            float a, bb, c, dd;
            up2(s0, a, bb); up2(s1, c, dd);
            g_omega[sig * 2 + 0] = __fdividef(a, bb + 1e-7f);
            g_omega[sig * 2 + 1] = __fdividef(c, dd + 1e-7f);
        }
    }

    // ---- outputs: which=0 -> ifft(h)=u0(t), which=1 -> ifft(kx)=u1(t)
#pragma unroll 1
    for (int which = 0; which < 2; which++) {
        float2 wA = wa_s[tid];
        float H0r = which ? kx0r : h0r, H0i = which ? kx0i : h0i;
        float H1r = which ? kx1r : h1r, H1i = which ? kx1i : h1i;
        float H2r = which ? kx2r : h2r, H2i = which ? kx2i : h2i;
        pack_store(X0, k1, k2, isT0, wA.x, wA.y,
                   H0r, H0i, H1r, H1i, H2r, H2i);
        fft256<+1, false, false>(X0u, X1u, X2u, X3u, tw0s, tw1s, tid, rawu, om_s, lamu, xsu);
        float* o = out + (size_t)(which + 1) * NTOT + (size_t)b * 65536 + d;
        o[(size_t)tv0 * 128] = z3f[2 * g0 + odd] * (1.0f / 512.0f);
        o[(size_t)tv1 * 128] = z3f[2 * g1 + odd] * (1.0f / 512.0f);
        o[(size_t)tv2 * 128] = z3f[2 * g2 + odd] * (1.0f / 512.0f);
        o[(size_t)tv3 * 128] = z3f[2 * g3 + odd] * (1.0f / 512.0f);
    }
}

// order[b]: argsort over K=2 of mean_d(omega). Stable: swap iff m1 < m0.
__global__ void order_kernel() {
    __shared__ float sm[64];
    int tid = threadIdx.x;
    if (tid < 64) {
        int b = tid >> 1, k = tid & 1;
        float s = 0.0f;
        for (int dd = 0; dd < 128; dd++)
            s += g_omega[((b << 7) + dd) * 2 + k];
        sm[tid] = s;
    }
    __syncthreads();
    if (tid < 32) g_swap[tid] = (sm[2 * tid + 1] < sm[2 * tid]) ? 1 : 0;
}

// zero x_trend; swap period/res segments where needed
__global__ void finalize_kernel(float* __restrict__ out) {
    int e = blockIdx.x * blockDim.x + threadIdx.x;
    if (e < NTOT) {
        out[e] = 0.0f;
        int b = e >> 16;
        if (g_swap[b]) {
            float a = out[NTOT + e];
            float c = out[2 * NTOT + e];
            out[NTOT + e] = c;
            out[2 * NTOT + e] = a;
        }
    }
}

extern "C" void kernel_launch(void* const* d_in, const int* in_sizes, int n_in,
                              void* d_out, int out_size) {
    const float* x = (const float*)d_in[0];
    float* out = (float*)d_out;
    vmd_main<<<NSIG, NT>>>(x, out);
    order_kernel<<<1, 64>>>();
    finalize_kernel<<<(NTOT + 255) / 256, 256>>>(out);
}

// round 17
// speedup vs baseline: 1.2284x; 1.2074x over previous
#include <cuda_runtime.h>

#define L      512
#define NT     128
#define NSIG   4096
#define NTOT   (32*512*128)

typedef unsigned long long ull;

__device__ float g_omega[NSIG * 2];
__device__ int   g_swap[32];

// ---- packed f32x2 helpers (complex = (re, im) in one 64-bit reg pair) ----
__device__ __forceinline__ ull pk2(float x, float y) {
    ull r; asm("mov.b64 %0,{%1,%2};" : "=l"(r) : "f"(x), "f"(y)); return r;
}
__device__ __forceinline__ void up2(ull a, float& x, float& y) {
    asm("mov.b64 {%0,%1},%2;" : "=f"(x), "=f"(y) : "l"(a));
}
__device__ __forceinline__ ull padd(ull a, ull b) {
    ull r; asm("add.rn.f32x2 %0,%1,%2;" : "=l"(r) : "l"(a), "l"(b)); return r;
}
__device__ __forceinline__ ull pfma(ull a, ull b, ull c) {
    ull r; asm("fma.rn.f32x2 %0,%1,%2,%3;" : "=l"(r) : "l"(a), "l"(b), "l"(c)); return r;
}
__device__ __forceinline__ ull psub(ull a, ull b, ull NEG1) { return pfma(b, NEG1, a); }
template<int SGN>
__device__ __forceinline__ ull pmuli(ull a) {
    float x, y; up2(a, x, y);
    return (SGN > 0) ? pk2(-y, x) : pk2(y, -x);
}
__device__ __forceinline__ ull pcmul(ull a, float wr, float wi) {
    float x, y; up2(a, x, y);
    return pk2(x * wr - y * wi, x * wi + y * wr);
}

// warp-wide reduce of a packed f32x2 pair (both lanes summed independently)
__device__ __forceinline__ ull preduce(ull v) {
#pragma unroll
    for (int o = 16; o; o >>= 1)
        v = padd(v, __shfl_xor_sync(0xffffffffu, v, o));
    return v;
}

// fold 256 raw float2 partials into om_s[2]; call on warp 2 (or warp 0 at end)
__device__ __forceinline__ void fold_om(const ull* raw, float* om_s, int ln) {
    ull s0 = padd(padd(raw[ln], raw[ln + 32]), padd(raw[ln + 64], raw[ln + 96]));
    ull s1 = padd(padd(raw[ln + 128], raw[ln + 160]), padd(raw[ln + 192], raw[ln + 224]));
    s0 = preduce(s0);
    s1 = preduce(s1);
    if (ln == 0) {
        float a, bb, c, dd;
        up2(s0, a, bb); up2(s1, c, dd);
        om_s[0] = __fdividef(a, bb + 1e-7f);
        om_s[1] = __fdividef(c, dd + 1e-7f);
    }
}

template<int SGN>
__device__ __forceinline__ void bfly8p(const ull c[8], ull dd[8], ull NEG1) {
    const float S2 = 0.70710678118654752f;
    ull t0 = padd(c[0], c[4]), t1 = psub(c[0], c[4], NEG1);
    ull t2 = padd(c[2], c[6]), t3 = pmuli<SGN>(psub(c[2], c[6], NEG1));
    ull u0 = padd(c[1], c[5]), u1 = psub(c[1], c[5], NEG1);
    ull u2 = padd(c[3], c[7]), u3 = pmuli<SGN>(psub(c[3], c[7], NEG1));
    ull E0 = padd(t0, t2), E2 = psub(t0, t2, NEG1);
    ull E1 = padd(t1, t3), E3 = psub(t1, t3, NEG1);
    ull O0 = padd(u0, u2), O2 = psub(u0, u2, NEG1);
    ull O1 = padd(u1, u3), O3 = psub(u1, u3, NEG1);
    ull o1 = pcmul(O1, S2, (SGN > 0) ? S2 : -S2);
    ull o2 = pmuli<SGN>(O2);
    ull o3 = pcmul(O3, -S2, (SGN > 0) ? S2 : -S2);
    dd[0] = padd(E0, O0); dd[4] = psub(E0, O0, NEG1);
    dd[1] = padd(E1, o1); dd[5] = psub(E1, o1, NEG1);
    dd[2] = padd(E2, o2); dd[6] = psub(E2, o2, NEG1);
    dd[3] = padd(E3, o3); dd[7] = psub(E3, o3, NEG1);
}

// 256-pt Stockham FFT, radices (8,8,4). X0 -> X1 -> X2 -> X3 (ull-aliased float2).
// X0/X3 natural; X1 XOR-swizzled; X2 padded (k + 72j). All LDS/STS conflict-free.
// Tables hold INVERSE twiddles; SGN=-1 conjugates => forward. No 1/N scaling.
// If OM: warp 2 folds the 256 raw float2 partials into om_s in the stage-0 window.
// First action is __syncthreads(); trailing sync.
template<int SGN, bool OM>
__device__ __forceinline__ void fft256(ull* X0, ull* X1, ull* X2, ull* X3,
                                       const float2* tw0, const float2* tw1, int tid,
                                       const ull* raw, float* om_s) {
    const ull NEG1 = pk2(-1.0f, -1.0f);
    __syncthreads();
    if (OM && (tid >> 5) == 2) fold_om(raw, om_s, tid & 31);
    if (tid < 32) {                 // stage 0: radix-8, X0 -> X1
        ull c[8], dd[8];
#pragma unroll
        for (int q = 0; q < 8; q++) c[q] = X0[tid + 32 * q];
        bfly8p<SGN>(c, dd, NEG1);
        const float2* tp = tw0 + 7 * tid;
#pragma unroll
        for (int p = 1; p < 8; p++) {
            float2 w = tp[p - 1];
            dd[p] = pcmul(dd[p], w.x, (SGN > 0) ? w.y : -w.y);
        }
        const int s = (tid >> 1) & 7;
        ull* st = X1 + 8 * tid;
#pragma unroll
        for (int p = 0; p < 8; p++) st[p ^ s] = dd[p];
    }
    __syncthreads();
    if (tid < 32) {                 // stage 1: radix-8, X1 -> X2
        const int j = tid >> 3, k = tid & 7;
        ull c[8], dd[8];
#pragma unroll
        for (int q = 0; q < 8; q++) { int l = tid + 32 * q; c[q] = X1[l ^ ((l >> 4) & 7)]; }
        bfly8p<SGN>(c, dd, NEG1);
        const float2* tp = tw1 + 7 * j;
#pragma unroll
        for (int p = 1; p < 8; p++) {
            float2 w = tp[p - 1];
            dd[p] = pcmul(dd[p], w.x, (SGN > 0) ? w.y : -w.y);
        }
        ull* st = X2 + (k + 72 * j);
#pragma unroll
        for (int p = 0; p < 8; p++) st[8 * p] = dd[p];
    }
    __syncthreads();
    if (tid < 64) {                 // stage 2: radix-4, X2 -> X3 (no twiddle)
        ull c[4];
#pragma unroll
        for (int q = 0; q < 4; q++) c[q] = X2[tid + 72 * q];
        ull t0 = padd(c[0], c[2]), t1 = psub(c[0], c[2], NEG1);
        ull t2 = padd(c[1], c[3]), t3 = pmuli<SGN>(psub(c[1], c[3], NEG1));
        X3[tid]       = padd(t0, t2);
        X3[tid + 64]  = padd(t1, t3);
        X3[tid + 128] = psub(t0, t2, NEG1);
        X3[tid + 192] = psub(t1, t3, NEG1);
    }
    __syncthreads();
}

// Pack ifft input for a Hermitian spectrum H (H2=conj(H1), H3=conj(H0) generic;
// t0: H0,H2 real, H3=conj(H1)). In[k1] = E1 + i*(D1*wA);
// In[k2]: generic (E1r+O1i, O1r-E1i), t0 (2H1r, -2H1i).
__device__ __forceinline__ void pack_store(float2* X0, int k1v, int k2v, bool isT0,
                                           float wAr, float wAi,
                                           float H0r, float H0i, float H1r, float H1i,
                                           float H2r, float H2i) {
    float E1r = H0r + H2r, E1i = H0i + H2i;
    float D1r = H0r - H2r, D1i = H0i - H2i;
    float O1r = D1r * wAr - D1i * wAi, O1i = D1r * wAi + D1i * wAr;
    X0[k1v] = make_float2(E1r - O1i, E1i + O1r);
    float gr = E1r + O1i, gi = O1r - E1i;
    X0[k2v] = make_float2(isT0 ? 2.0f * H1r : gr, isT0 ? -2.0f * H1i : gi);
}

// One CTA = one (b,d) signal. Spectra register-resident; thread wt owns bins
// {wt, 256-wt, 256+wt, 512-wt} (wt=0: {0,128,256,384}). kx=Herm(U1) carried;
// Herm slots 2,3 by conjugation. LAMBDA STAIRCASE: the per-iter ifft (needed
// only for lambda) runs at iters {0..9 (w=1), 13,17,...,45 (w=4), 48 (w=3)}
// — total weight 49 matches the exact accumulation, no tail lag. Omega is
// exact every iter: in-window warp-2 fold on FFT iters, 2-barrier fold else.
__global__ void __launch_bounds__(NT, 8) vmd_main(const float* __restrict__ x,
                                                  float* __restrict__ out) {
    __shared__ float2 X0[256], X1[256], X2[280], X3[256];
    __shared__ float2 tw0s[224], tw1s[28];
    __shared__ float2 raw2[256];       // (n0,den0)[tid], (n1,den1)[tid+128]
    __shared__ float om_s[2];
    __shared__ float xs_s[512];        // xs_s[slot*128 + tid]
    __shared__ float2 wa_s[128];       // wA per thread
    ull* X0u = reinterpret_cast<ull*>(X0);
    ull* X1u = reinterpret_cast<ull*>(X1);
    ull* X2u = reinterpret_cast<ull*>(X2);
    ull* X3u = reinterpret_cast<ull*>(X3);
    ull* rawu = reinterpret_cast<ull*>(raw2);

    const int tid = threadIdx.x;
    const int sig = blockIdx.x;
    const int b = sig >> 7, d = sig & 127;
    const float* xp = x + (size_t)b * 65536 + d;

    // inverse twiddle tables: tw0[7j+p-1]=cis(2pi j p/256) j<32; tw1: /32, j<4
    for (int idx = tid; idx < 224 + 28; idx += NT) {
        if (idx < 224) {
            int j = idx / 7, pm = idx - 7 * j + 1;
            float sv, cv;
            sincosf(6.283185307179586f * (float)(j * pm) * (1.0f / 256.0f), &sv, &cv);
            tw0s[idx] = make_float2(cv, sv);
        } else {
            int r = idx - 224;
            int j = r / 7, pm = r - 7 * j + 1;
            float sv, cv;
            sincosf(6.283185307179586f * (float)(j * pm) * (1.0f / 32.0f), &sv, &cv);
            tw1s[r] = make_float2(cv, sv);
        }
    }

    const bool isT0 = (tid == 0);
    const int tv0 = isT0 ? 0   : tid;
    const int tv1 = isT0 ? 128 : 256 - tid;
    const int tv2 = isT0 ? 256 : 256 + tid;
    const int tv3 = isT0 ? 384 : 512 - tid;
    const float f0 = (float)tv0 * (1.0f / 512.0f);
    const float f1 = (float)tv1 * (1.0f / 512.0f);
    const float f2 = (float)(tv2 - 512) * (1.0f / 512.0f);
    const float f3 = (float)(tv3 - 512) * (1.0f / 512.0f);
    const int k1 = tv0;            // packs slots (0,2)
    const int k2 = tv1 & 255;      // packs slots (1,3)
    const int g0 = tv0 >> 1, g1 = tv1 >> 1, g2 = tv2 >> 1, g3 = tv3 >> 1;
    const int odd = tv0 & 1;
    float wBr, wBi;   // prologue-only
    {
        float ar, ai;
        sincosf(6.283185307179586f * f0, &ai, &ar);
        sincosf(6.283185307179586f * f1, &wBi, &wBr);
        wa_s[tid] = make_float2(ar, ai);
        xs_s[tid]       = xp[(size_t)tv0 * 128];
        xs_s[tid + 128] = xp[(size_t)tv1 * 128];
        xs_s[tid + 256] = xp[(size_t)tv2 * 128];
        xs_s[tid + 384] = xp[(size_t)tv3 * 128];
    }

    // forward: pack z[m] = x[2m] + i x[2m+1], one 256-pt forward FFT
#pragma unroll
    for (int m = tid; m < 256; m += NT) {
        float ev = xp[(size_t)(2 * m) * 128];
        float ov = xp[(size_t)(2 * m + 1) * 128];
        X0[m] = make_float2(ev, ov);
    }
    fft256<-1, false>(X0u, X1u, X2u, X3u, tw0s, tw1s, tid, rawu, om_s);
    float X0r, X0i, X1r, X1i, X2r, X2i, X3r, X3i;
    {
        float2 wA = wa_s[tid];
        float2 Zt = X3[k1], Zk = X3[k2];
        float2 M1 = isT0 ? Zt : Zk;
        float2 M2 = isT0 ? Zk : Zt;
        float Er = 0.5f * (Zt.x + M1.x), Ei = 0.5f * (Zt.y - M1.y);
        float Dr = Zt.x - M1.x,         Di = Zt.y + M1.y;
        float Or = 0.5f * Di,           Oi = -0.5f * Dr;
        float cr = wA.x * Or + wA.y * Oi, ci = wA.x * Oi - wA.y * Or;
        X0r = Er + cr; X0i = Ei + ci;
        X2r = Er - cr; X2i = Ei - ci;
        float Er2 = 0.5f * (Zk.x + M2.x), Ei2 = 0.5f * (Zk.y - M2.y);
        float Dr2 = Zk.x - M2.x,          Di2 = Zk.y + M2.y;
        float Or2 = 0.5f * Di2,           Oi2 = -0.5f * Dr2;
        float cr2 = wBr * Or2 + wBi * Oi2, ci2 = wBr * Oi2 - wBi * Or2;
        X1r = Er2 + cr2; X1i = Ei2 + ci2;
        X3r = Er2 - cr2; X3i = Ei2 - ci2;
    }

    // loop-carried: kx = Herm(U1) (init 0), h = Herm(U0) (epilogue use)
    float kx0r = 0.f, kx0i = 0.f, kx1r = 0.f, kx1i = 0.f;
    float kx2r = 0.f, kx2i = 0.f, kx3r = 0.f, kx3i = 0.f;
    float h0r = 0.f, h0i = 0.f, h1r = 0.f, h1i = 0.f;
    float h2r = 0.f, h2i = 0.f, h3r = 0.f, h3i = 0.f;
    float l0 = 0.f, l1 = 0.f, l2 = 0.f, l3 = 0.f;
    float om0 = 0.0f, om1 = 0.0f;
    const float* z3f = reinterpret_cast<const float*>(X3);

    for (int iter = 0; iter < 50; iter++) {
        // ---- Pass A (mirror-free): U0 = (X - kx + lam'/2) * q0
        float df, q;
        float u0r0, u0i0, u0r1, u0i1, u0r2, u0i2, u0r3, u0i3;
        df = f0 - om0; q = __frcp_rn(fmaf(1600.0f * df, df, 1.0f));
        u0r0 = (X0r - kx0r + 0.5f * l2) * q; u0i0 = (X0i - kx0i) * q;
        df = f1 - om0; q = __frcp_rn(fmaf(1600.0f * df, df, 1.0f));
        u0r1 = (X1r - kx1r + 0.5f * l3) * q; u0i1 = (X1i - kx1i) * q;
        df = f2 - om0; q = __frcp_rn(fmaf(1600.0f * df, df, 1.0f));
        u0r2 = (X2r - kx2r + 0.5f * l0) * q; u0i2 = (X2i - kx2i) * q;
        df = f3 - om0; q = __frcp_rn(fmaf(1600.0f * df, df, 1.0f));
        u0r3 = (X3r - kx3r + 0.5f * l1) * q; u0i3 = (X3i - kx3i) * q;

        // ---- Pass B: h = Herm(U0) via conj pairing; omega0 partials; U1 update
        {
            float m0r = isT0 ? u0r0 : u0r3, m0i = isT0 ? u0i0 : u0i3;
            float m1r = isT0 ? u0r3 : u0r2, m1i = isT0 ? u0i3 : u0i2;
            h0r = 0.5f * (u0r0 + m0r); h0i = 0.5f * (u0i0 - m0i);
            h1r = 0.5f * (u0r1 + m1r); h1i = 0.5f * (u0i1 - m1i);
            h2r = isT0 ? u0r2 : h1r;   h2i = isT0 ? 0.0f : -h1i;
            h3r = isT0 ? h1r : h0r;    h3i = -(isT0 ? h1i : h0i);
        }
        float p0 = h0r * h0r + h0i * h0i;
        float p1 = h1r * h1r + h1i * h1i;
        raw2[tid] = make_float2(f0 * p0 + f1 * p1, p0 + p1);
        float u1r0, u1i0, u1r1, u1i1, u1r2, u1i2, u1r3, u1i3;
        df = f0 - om1; q = __frcp_rn(fmaf(1600.0f * df, df, 1.0f));
        u1r0 = (X0r - h0r + 0.5f * l2) * q; u1i0 = (X0i - h0i) * q;
        df = f1 - om1; q = __frcp_rn(fmaf(1600.0f * df, df, 1.0f));
        u1r1 = (X1r - h1r + 0.5f * l3) * q; u1i1 = (X1i - h1i) * q;
        df = f2 - om1; q = __frcp_rn(fmaf(1600.0f * df, df, 1.0f));
        u1r2 = (X2r - h2r + 0.5f * l0) * q; u1i2 = (X2i - h2i) * q;
        df = f3 - om1; q = __frcp_rn(fmaf(1600.0f * df, df, 1.0f));
        u1r3 = (X3r - h3r + 0.5f * l1) * q; u1i3 = (X3i - h3i) * q;

        // ---- Pass C: kx = Herm(U1) via conj pairing; omega1 partials
        {
            float m0r = isT0 ? u1r0 : u1r3, m0i = isT0 ? u1i0 : u1i3;
            float m1r = isT0 ? u1r3 : u1r2, m1i = isT0 ? u1i3 : u1i2;
            kx0r = 0.5f * (u1r0 + m0r); kx0i = 0.5f * (u1i0 - m0i);
            kx1r = 0.5f * (u1r1 + m1r); kx1i = 0.5f * (u1i1 - m1i);
            kx2r = isT0 ? u1r2 : kx1r;  kx2i = isT0 ? 0.0f : -kx1i;
            kx3r = isT0 ? kx1r : kx0r;  kx3i = -(isT0 ? kx1i : kx0i);
        }
        p0 = kx0r * kx0r + kx0i * kx0i;
        p1 = kx1r * kx1r + kx1i * kx1i;
        raw2[tid + 128] = make_float2(f0 * p0 + f1 * p1, p0 + p1);

        if (iter == 49) break;   // final omega handled after the loop

        // lambda-staircase schedule: FFT+lambda at {0..9, 13,17,...,45, 48}
        bool doF = (iter < 10) || (iter >= 13 && iter <= 45 && ((iter - 13) & 3) == 0)
                   || (iter == 48);
        if (doF) {
            {
                float2 wA = wa_s[tid];
                float H0r = h0r + kx0r, H0i = h0i + kx0i;
                float H1r = h1r + kx1r, H1i = h1i + kx1i;
                float H2r = h2r + kx2r, H2i = h2i + kx2i;
                pack_store(X0, k1, k2, isT0, wA.x, wA.y,
                           H0r, H0i, H1r, H1i, H2r, H2i);
            }
            fft256<+1, true>(X0u, X1u, X2u, X3u, tw0s, tw1s, tid, rawu, om_s);
            om0 = om_s[0];
            om1 = om_s[1];
            float wt = (iter < 10) ? 0.001f : ((iter == 48) ? 0.003f : 0.004f);
            l0 = fmaf(wt, xs_s[tid]       - z3f[2 * g0 + odd] * (1.0f / 512.0f), l0);
            l1 = fmaf(wt, xs_s[tid + 128] - z3f[2 * g1 + odd] * (1.0f / 512.0f), l1);
            l2 = fmaf(wt, xs_s[tid + 256] - z3f[2 * g2 + odd] * (1.0f / 512.0f), l2);
            l3 = fmaf(wt, xs_s[tid + 384] - z3f[2 * g3 + odd] * (1.0f / 512.0f), l3);
        } else {
            // omega refresh only: 2-barrier warp-2 fold
            __syncthreads();
            if ((tid >> 5) == 2) fold_om(rawu, om_s, tid & 31);
            __syncthreads();
            om0 = om_s[0];
            om1 = om_s[1];
        }
    }

    // final omega from the iter-49 partials (warp 0, one time)
    __syncthreads();
    if (tid < 32) {
        fold_om(rawu, om_s, tid);
        if (tid == 0) {
            g_omega[sig * 2 + 0] = om_s[0];
            g_omega[sig * 2 + 1] = om_s[1];
        }
    }

    // ---- outputs: which=0 -> ifft(h)=u0(t), which=1 -> ifft(kx)=u1(t)
#pragma unroll 1
    for (int which = 0; which < 2; which++) {
        float2 wA = wa_s[tid];
        float H0r = which ? kx0r : h0r, H0i = which ? kx0i : h0i;
        float H1r = which ? kx1r : h1r, H1i = which ? kx1i : h1i;
        float H2r = which ? kx2r : h2r, H2i = which ? kx2i : h2i;
        pack_store(X0, k1, k2, isT0, wA.x, wA.y,
                   H0r, H0i, H1r, H1i, H2r, H2i);
        fft256<+1, false>(X0u, X1u, X2u, X3u, tw0s, tw1s, tid, rawu, om_s);
        float* o = out + (size_t)(which + 1) * NTOT + (size_t)b * 65536 + d;
        o[(size_t)tv0 * 128] = z3f[2 * g0 + odd] * (1.0f / 512.0f);
        o[(size_t)tv1 * 128] = z3f[2 * g1 + odd] * (1.0f / 512.0f);
        o[(size_t)tv2 * 128] = z3f[2 * g2 + odd] * (1.0f / 512.0f);
        o[(size_t)tv3 * 128] = z3f[2 * g3 + odd] * (1.0f / 512.0f);
    }
}

// order[b]: argsort over K=2 of mean_d(omega). Stable: swap iff m1 < m0.
__global__ void order_kernel() {
    __shared__ float sm[64];
    int tid = threadIdx.x;
    if (tid < 64) {
        int b = tid >> 1, k = tid & 1;
        float s = 0.0f;
        for (int dd = 0; dd < 128; dd++)
            s += g_omega[((b << 7) + dd) * 2 + k];
        sm[tid] = s;
    }
    __syncthreads();
    if (tid < 32) g_swap[tid] = (sm[2 * tid + 1] < sm[2 * tid]) ? 1 : 0;
}

// zero x_trend; swap period/res segments where needed
__global__ void finalize_kernel(float* __restrict__ out) {
    int e = blockIdx.x * blockDim.x + threadIdx.x;
    if (e < NTOT) {
        out[e] = 0.0f;
        int b = e >> 16;
        if (g_swap[b]) {
            float a = out[NTOT + e];
            float c = out[2 * NTOT + e];
            out[NTOT + e] = c;
            out[2 * NTOT + e] = a;
        }
    }
}

extern "C" void kernel_launch(void* const* d_in, const int* in_sizes, int n_in,
                              void* d_out, int out_size) {
    const float* x = (const float*)d_in[0];
    float* out = (float*)d_out;
    vmd_main<<<NSIG, NT>>>(x, out);
    order_kernel<<<1, 64>>>();
    finalize_kernel<<<(NTOT + 255) / 256, 256>>>(out);
}